// round 3
// baseline (speedup 1.0000x reference)
#include <cuda_runtime.h>
#include <cuda_bf16.h>
#include <cuda_fp16.h>
#include <cstdint>

#define HW 512
#define NB 8
#define NC 32

// R scratch: 30 planes [j*3+ky][b][y][x] fp16 = 126 MB
__device__ __half g_R[(size_t)30 * NB * HW * HW];

// ---------------- smem layout (pass 1) ----------------
// A tile : bytes [0, 40960)   x_s[m][k] fp16, row stride 40 halfs (80 B)
// Y tile : bytes [0, 196608)  Y[n][m] fp32, 96 planes of 512 (overlaps A;
//                             written only after all ldmatrix reads of A)
// W tile : bytes [196608, 202752)  w_s[n][k] fp16, 96 x 32
#define A_OFF 0
#define Y_OFF 0
#define W_OFF 196608
#define SMEM_SIZE 202752

__device__ __forceinline__ uint32_t smem_to_u32(const void* smem_ptr) {
    uint32_t addr;
    asm("{ .reg .u64 tmp; cvta.to.shared.u64 tmp, %1; cvt.u32.u64 %0, tmp; }"
        : "=r"(addr) : "l"(smem_ptr));
    return addr;
}

__device__ __forceinline__ void ldmatrix_x4(
    uint32_t& r0, uint32_t& r1, uint32_t& r2, uint32_t& r3, uint32_t addr)
{
    asm volatile(
        "ldmatrix.sync.aligned.m8n8.x4.shared.b16 {%0,%1,%2,%3}, [%4];"
        : "=r"(r0), "=r"(r1), "=r"(r2), "=r"(r3) : "r"(addr));
}

__device__ __forceinline__ void mma16816(
    float* d, const uint32_t* a, uint32_t b0, uint32_t b1)
{
    asm volatile(
        "mma.sync.aligned.m16n8k16.row.col.f32.f16.f16.f32 "
        "{%0,%1,%2,%3}, {%4,%5,%6,%7}, {%8,%9}, {%0,%1,%2,%3};"
        : "+f"(d[0]), "+f"(d[1]), "+f"(d[2]), "+f"(d[3])
        : "r"(a[0]), "r"(a[1]), "r"(a[2]), "r"(a[3]), "r"(b0), "r"(b1));
}

// =====================================================================
// Pass 1: one CTA per image row (b, y). 512 threads = 16 warps.
//   GEMM: Y[n][m] = sum_c x_s[m][c] * w_s[n][c]   (fp16 in, fp32 accum)
//     n = j*9 + ky*3 + kx (90 used, padded to 96), m = pixel 0..511
//   Then horizontal (kx) fold -> R[(j,ky)] fp16 in global scratch.
//   Passthrough copy of x (channels 0..31) fused into the A fill.
// =====================================================================
__global__ void __launch_bounds__(512, 1)
msd_pass1(const float* __restrict__ x, const float* __restrict__ W,
          float* __restrict__ out)
{
    extern __shared__ char smem[];
    const uint32_t smem_base = smem_to_u32(smem);
    const int tid = threadIdx.x;
    const int wid = tid >> 5;
    const int lid = tid & 31;
    const int y = blockIdx.x;
    const int b = blockIdx.y;

    __half* ws = reinterpret_cast<__half*>(smem + W_OFF);
    float*  Ys = reinterpret_cast<float*>(smem + Y_OFF);

    // ---- fill W operand: w_s[n][c], n = j*9+ky*3+kx ----
    for (int idx = tid; idx < 96 * 32; idx += 512) {
        int n = idx >> 5, c = idx & 31;
        float w = 0.0f;
        if (n < 90) {
            int j = n / 9, rem = n - j * 9;
            int ky = rem / 3, kx = rem - ky * 3;
            w = W[((j * 32 + c) * 3 + ky) * 3 + kx];
        }
        ws[n * 32 + c] = __float2half(w);
    }

    // ---- fill A operand (x_s[m][c], stride 40) + fused passthrough ----
    const size_t xbase = (size_t)b * NC * HW * HW + (size_t)y * HW;
    const size_t obase = (size_t)b * 42 * HW * HW + (size_t)y * HW;
    #pragma unroll 4
    for (int idx = tid; idx < NC * HW; idx += 512) {
        int c = idx >> 9, m = idx & 511;
        float v = x[xbase + (size_t)c * (HW * HW) + m];
        out[obase + (size_t)c * (HW * HW) + m] = v;   // passthrough
        *reinterpret_cast<__half*>(smem + A_OFF + m * 80 + c * 2) =
            __float2half(v);
    }
    __syncthreads();

    // ---- load A fragments (2 m16 tiles x 2 k-halves per warp) ----
    const int mb = wid * 32;
    const int r8 = lid & 7, t8 = lid >> 3;
    uint32_t afr[2][2][4];
    #pragma unroll
    for (int mt = 0; mt < 2; mt++)
        #pragma unroll
        for (int kh = 0; kh < 2; kh++) {
            int row = mb + mt * 16 + r8 + (t8 & 1) * 8;
            int col = kh * 16 + (t8 >> 1) * 8;
            uint32_t addr = smem_base + A_OFF + row * 80 + col * 2;
            ldmatrix_x4(afr[mt][kh][0], afr[mt][kh][1],
                        afr[mt][kh][2], afr[mt][kh][3], addr);
        }
    __syncthreads();   // all A reads done -> Y may overwrite A region

    // ---- MMA in two N-halves (6 n-blocks each) to bound registers ----
    const int g = lid >> 2, t = lid & 3;
    #pragma unroll
    for (int half = 0; half < 2; half++) {
        float acc[6][2][4];
        #pragma unroll
        for (int nb = 0; nb < 6; nb++)
            #pragma unroll
            for (int mt = 0; mt < 2; mt++)
                #pragma unroll
                for (int i = 0; i < 4; i++) acc[nb][mt][i] = 0.0f;

        #pragma unroll
        for (int nb = 0; nb < 6; nb++) {
            int n0 = (half * 6 + nb) * 8;
            #pragma unroll
            for (int kh = 0; kh < 2; kh++) {
                const __half* wp = ws + (n0 + g) * 32 + kh * 16 + 2 * t;
                uint32_t b0 = *reinterpret_cast<const uint32_t*>(wp);
                uint32_t b1 = *reinterpret_cast<const uint32_t*>(wp + 8);
                mma16816(acc[nb][0], afr[0][kh], b0, b1);
                mma16816(acc[nb][1], afr[1][kh], b0, b1);
            }
        }
        // ---- scatter accumulators into Y[n][m] (fp32 smem) ----
        #pragma unroll
        for (int nb = 0; nb < 6; nb++) {
            int n0 = (half * 6 + nb) * 8;
            #pragma unroll
            for (int mt = 0; mt < 2; mt++) {
                int mrow = mb + mt * 16 + g;
                Ys[(n0 + 2 * t)     * HW + mrow]     = acc[nb][mt][0];
                Ys[(n0 + 2 * t + 1) * HW + mrow]     = acc[nb][mt][1];
                Ys[(n0 + 2 * t)     * HW + mrow + 8] = acc[nb][mt][2];
                Ys[(n0 + 2 * t + 1) * HW + mrow + 8] = acc[nb][mt][3];
            }
        }
    }
    __syncthreads();

    // ---- horizontal (kx) fold -> R fp16 ----
    const int m = tid;
    const size_t rpix = ((size_t)b * HW + y) * HW + m;
    #pragma unroll
    for (int j = 0; j < 10; j++) {
        int d = j + 1;
        #pragma unroll
        for (int ky = 0; ky < 3; ky++) {
            int n = j * 9 + ky * 3;
            float acc = Ys[(n + 1) * HW + m];
            if (m - d >= 0) acc += Ys[n * HW + (m - d)];
            if (m + d < HW) acc += Ys[(n + 2) * HW + (m + d)];
            g_R[(size_t)(j * 3 + ky) * ((size_t)NB * HW * HW) + rpix] =
                __float2half(acc);
        }
    }
}

// =====================================================================
// Pass 2: vertical (ky) fold + bias. 4 pixels per thread, float4 store.
// =====================================================================
__global__ void __launch_bounds__(256)
msd_pass2(const float* __restrict__ bias, float* __restrict__ out)
{
    int idx4 = blockIdx.x * 256 + threadIdx.x;
    int x4 = idx4 & 127;
    int y  = (idx4 >> 7) & 511;
    int t  = idx4 >> 16;
    int j  = t % 10;
    int b  = t / 10;
    int d  = j + 1;
    float bj = __ldg(bias + j);
    float a0 = bj, a1 = bj, a2 = bj, a3 = bj;
    #pragma unroll
    for (int ky = 0; ky < 3; ky++) {
        int y2 = y + (ky - 1) * d;
        if (y2 < 0 || y2 >= HW) continue;
        const __half2* p = reinterpret_cast<const __half2*>(
            g_R + (size_t)(j * 3 + ky) * ((size_t)NB * HW * HW)
                + ((size_t)b * HW + y2) * HW + (size_t)x4 * 4);
        float2 f0 = __half22float2(p[0]);
        float2 f1 = __half22float2(p[1]);
        a0 += f0.x; a1 += f0.y; a2 += f1.x; a3 += f1.y;
    }
    float4 v = make_float4(a0, a1, a2, a3);
    *reinterpret_cast<float4*>(
        out + ((size_t)(b * 42 + 32 + j) * HW + y) * HW + (size_t)x4 * 4) = v;
}

// =====================================================================
extern "C" void kernel_launch(void* const* d_in, const int* in_sizes, int n_in,
                              void* d_out, int out_size)
{
    const float* x = nullptr;
    const float* W = nullptr;
    const float* bias = nullptr;
    for (int i = 0; i < n_in; i++) {
        if (in_sizes[i] == 8 * 32 * 512 * 512) x    = (const float*)d_in[i];
        else if (in_sizes[i] == 2880)          W    = (const float*)d_in[i];
        else if (in_sizes[i] == 10)            bias = (const float*)d_in[i];
    }
    float* out = (float*)d_out;

    cudaFuncSetAttribute(msd_pass1,
                         cudaFuncAttributeMaxDynamicSharedMemorySize, SMEM_SIZE);

    dim3 g1(HW, NB);
    msd_pass1<<<g1, 512, SMEM_SIZE>>>(x, W, out);

    int n4 = NB * 10 * HW * HW / 4;          // 5,242,880 quads
    msd_pass2<<<n4 / 256, 256>>>(bias, out);
}

// round 4
// speedup vs baseline: 1.5562x; 1.5562x over previous
#include <cuda_runtime.h>
#include <cuda_bf16.h>
#include <cuda_fp16.h>
#include <cstdint>

#define HW 512
#define NB 8
#define NC 32

// R scratch: 30 planes [j*3+ky][b][y][x] fp16 = 126 MB
__device__ __half g_R[(size_t)30 * NB * HW * HW];

// ---------------- smem layout (pass 1) ----------------
// Y tile : halfs, [96][520] at byte 0   (96*520*2 = 99840 B)
// A tile : halfs, [512][40] at byte 0   (40960 B, overlaps Y; all ldmatrix
//                                        reads complete before Y is written)
// W tile : halfs, [96][32]  at byte 99840 (6144 B)
#define Y_STRIDE 520
#define W_OFF 99840
#define SMEM_SIZE 105984

__device__ __forceinline__ uint32_t smem_to_u32(const void* smem_ptr) {
    uint32_t addr;
    asm("{ .reg .u64 tmp; cvta.to.shared.u64 tmp, %1; cvt.u32.u64 %0, tmp; }"
        : "=r"(addr) : "l"(smem_ptr));
    return addr;
}

__device__ __forceinline__ void ldmatrix_x4(
    uint32_t& r0, uint32_t& r1, uint32_t& r2, uint32_t& r3, uint32_t addr)
{
    asm volatile(
        "ldmatrix.sync.aligned.m8n8.x4.shared.b16 {%0,%1,%2,%3}, [%4];"
        : "=r"(r0), "=r"(r1), "=r"(r2), "=r"(r3) : "r"(addr));
}

__device__ __forceinline__ void mma16816(
    float* d, const uint32_t* a, uint32_t b0, uint32_t b1)
{
    asm volatile(
        "mma.sync.aligned.m16n8k16.row.col.f32.f16.f16.f32 "
        "{%0,%1,%2,%3}, {%4,%5,%6,%7}, {%8,%9}, {%0,%1,%2,%3};"
        : "+f"(d[0]), "+f"(d[1]), "+f"(d[2]), "+f"(d[3])
        : "r"(a[0]), "r"(a[1]), "r"(a[2]), "r"(a[3]), "r"(b0), "r"(b1));
}

// =====================================================================
// Pass 1: one CTA per image row (b, y). 512 threads = 16 warps, occ 2.
//   GEMM: Y[n][m] = sum_c x[m][c] * w[n][c]  (fp16 in, fp32 accum, fp16 out)
//     n = j*9 + ky*3 + kx (90 used, padded to 96), m = pixel 0..511
//   Horizontal (kx) fold -> R[(j,ky)] fp16 in global scratch.
//   Passthrough copy of x (channels 0..31) fused into the A fill.
// =====================================================================
__global__ void __launch_bounds__(512, 2)
msd_pass1(const float* __restrict__ x, const float* __restrict__ W,
          float* __restrict__ out)
{
    extern __shared__ char smem[];
    const uint32_t smem_base = smem_to_u32(smem);
    const int tid = threadIdx.x;
    const int wid = tid >> 5;
    const int lid = tid & 31;
    const int y = blockIdx.x;
    const int b = blockIdx.y;

    __half* ws = reinterpret_cast<__half*>(smem + W_OFF);
    __half* Ys = reinterpret_cast<__half*>(smem);

    // ---- fill W operand: w_s[n][c], n = j*9+ky*3+kx ----
    for (int idx = tid; idx < 96 * 32; idx += 512) {
        int n = idx >> 5, c = idx & 31;
        float w = 0.0f;
        if (n < 90) {
            int j = n / 9, rem = n - j * 9;
            int ky = rem / 3, kx = rem - ky * 3;
            w = W[((j * 32 + c) * 3 + ky) * 3 + kx];
        }
        ws[n * 32 + c] = __float2half(w);
    }

    // ---- fill A operand: thread m owns pixel m (MLP=32, STS.128 x4) ----
    const size_t xbase = (size_t)b * NC * HW * HW + (size_t)y * HW;
    const size_t obase = (size_t)b * 42 * HW * HW + (size_t)y * HW;
    {
        const int m = tid;
        float v[32];
        #pragma unroll
        for (int c = 0; c < 32; c++)
            v[c] = x[xbase + (size_t)c * (HW * HW) + m];
        #pragma unroll
        for (int c = 0; c < 32; c++)
            out[obase + (size_t)c * (HW * HW) + m] = v[c];   // passthrough
        uint32_t h2[16];
        #pragma unroll
        for (int i = 0; i < 16; i++) {
            __half2 p = __floats2half2_rn(v[2 * i], v[2 * i + 1]);
            h2[i] = *reinterpret_cast<uint32_t*>(&p);
        }
        uint4* arow = reinterpret_cast<uint4*>(smem + m * 80);
        #pragma unroll
        for (int k = 0; k < 4; k++)
            arow[k] = make_uint4(h2[4 * k], h2[4 * k + 1],
                                 h2[4 * k + 2], h2[4 * k + 3]);
    }
    __syncthreads();

    // ---- load A fragments (2 m16 tiles x 2 k-halves per warp) ----
    const int mb = wid * 32;
    const int r8 = lid & 7, t8 = lid >> 3;
    uint32_t afr[2][2][4];
    #pragma unroll
    for (int mt = 0; mt < 2; mt++)
        #pragma unroll
        for (int kh = 0; kh < 2; kh++) {
            int row = mb + mt * 16 + r8 + (t8 & 1) * 8;
            int col = kh * 16 + (t8 >> 1) * 8;
            uint32_t addr = smem_base + row * 80 + col * 2;
            ldmatrix_x4(afr[mt][kh][0], afr[mt][kh][1],
                        afr[mt][kh][2], afr[mt][kh][3], addr);
        }
    __syncthreads();   // all A reads done -> Y may overwrite A region

    // ---- MMA: per M-tile, 3 N-groups of 4 n-blocks (16 acc regs) ----
    const int g = lid >> 2, t = lid & 3;
    #pragma unroll
    for (int mt = 0; mt < 2; mt++) {
        const int mrow = mb + mt * 16 + g;
        #pragma unroll
        for (int grp = 0; grp < 3; grp++) {
            float acc[4][4];
            #pragma unroll
            for (int nb = 0; nb < 4; nb++)
                #pragma unroll
                for (int i = 0; i < 4; i++) acc[nb][i] = 0.0f;

            #pragma unroll
            for (int nb = 0; nb < 4; nb++) {
                int n0 = (grp * 4 + nb) * 8;
                #pragma unroll
                for (int kh = 0; kh < 2; kh++) {
                    const __half* wp = ws + (n0 + g) * 32 + kh * 16 + 2 * t;
                    uint32_t b0 = *reinterpret_cast<const uint32_t*>(wp);
                    uint32_t b1 = *reinterpret_cast<const uint32_t*>(wp + 8);
                    mma16816(acc[nb], afr[mt][kh], b0, b1);
                }
            }
            // scatter accumulators into Y[n][m] (fp16 smem)
            #pragma unroll
            for (int nb = 0; nb < 4; nb++) {
                int n0 = (grp * 4 + nb) * 8;
                Ys[(n0 + 2 * t)     * Y_STRIDE + mrow]     = __float2half(acc[nb][0]);
                Ys[(n0 + 2 * t + 1) * Y_STRIDE + mrow]     = __float2half(acc[nb][1]);
                Ys[(n0 + 2 * t)     * Y_STRIDE + mrow + 8] = __float2half(acc[nb][2]);
                Ys[(n0 + 2 * t + 1) * Y_STRIDE + mrow + 8] = __float2half(acc[nb][3]);
            }
        }
    }
    __syncthreads();

    // ---- horizontal (kx) fold -> R fp16 ----
    const int m = tid;
    const size_t rpix = ((size_t)b * HW + y) * HW + m;
    #pragma unroll
    for (int j = 0; j < 10; j++) {
        int d = j + 1;
        #pragma unroll
        for (int ky = 0; ky < 3; ky++) {
            int n = j * 9 + ky * 3;
            float acc = __half2float(Ys[(n + 1) * Y_STRIDE + m]);
            if (m - d >= 0) acc += __half2float(Ys[n * Y_STRIDE + (m - d)]);
            if (m + d < HW) acc += __half2float(Ys[(n + 2) * Y_STRIDE + (m + d)]);
            g_R[(size_t)(j * 3 + ky) * ((size_t)NB * HW * HW) + rpix] =
                __float2half(acc);
        }
    }
}

// =====================================================================
// Pass 2: vertical (ky) fold + bias. 4 pixels per thread, float4 store.
// =====================================================================
__global__ void __launch_bounds__(256)
msd_pass2(const float* __restrict__ bias, float* __restrict__ out)
{
    int idx4 = blockIdx.x * 256 + threadIdx.x;
    int x4 = idx4 & 127;
    int y  = (idx4 >> 7) & 511;
    int t  = idx4 >> 16;
    int j  = t % 10;
    int b  = t / 10;
    int d  = j + 1;
    float bj = __ldg(bias + j);
    float a0 = bj, a1 = bj, a2 = bj, a3 = bj;
    #pragma unroll
    for (int ky = 0; ky < 3; ky++) {
        int y2 = y + (ky - 1) * d;
        if (y2 < 0 || y2 >= HW) continue;
        const __half2* p = reinterpret_cast<const __half2*>(
            g_R + (size_t)(j * 3 + ky) * ((size_t)NB * HW * HW)
                + ((size_t)b * HW + y2) * HW + (size_t)x4 * 4);
        float2 f0 = __half22float2(p[0]);
        float2 f1 = __half22float2(p[1]);
        a0 += f0.x; a1 += f0.y; a2 += f1.x; a3 += f1.y;
    }
    float4 v = make_float4(a0, a1, a2, a3);
    *reinterpret_cast<float4*>(
        out + ((size_t)(b * 42 + 32 + j) * HW + y) * HW + (size_t)x4 * 4) = v;
}

// =====================================================================
extern "C" void kernel_launch(void* const* d_in, const int* in_sizes, int n_in,
                              void* d_out, int out_size)
{
    const float* x = nullptr;
    const float* W = nullptr;
    const float* bias = nullptr;
    for (int i = 0; i < n_in; i++) {
        if (in_sizes[i] == 8 * 32 * 512 * 512) x    = (const float*)d_in[i];
        else if (in_sizes[i] == 2880)          W    = (const float*)d_in[i];
        else if (in_sizes[i] == 10)            bias = (const float*)d_in[i];
    }
    float* out = (float*)d_out;

    cudaFuncSetAttribute(msd_pass1,
                         cudaFuncAttributeMaxDynamicSharedMemorySize, SMEM_SIZE);

    dim3 g1(HW, NB);
    msd_pass1<<<g1, 512, SMEM_SIZE>>>(x, W, out);

    int n4 = NB * 10 * HW * HW / 4;          // 5,242,880 quads
    msd_pass2<<<n4 / 256, 256>>>(bias, out);
}

// round 5
// speedup vs baseline: 1.8796x; 1.2078x over previous
#include <cuda_runtime.h>
#include <cuda_bf16.h>
#include <cuda_fp16.h>
#include <cstdint>

#define HW 512
#define NB 8
#define NC 32

// R scratch: 30 planes [j*3+ky][b][y][x] fp16 = 126 MB
__device__ __half g_R[(size_t)30 * NB * HW * HW];

// ---------------- smem layout (pass 1) ----------------
// Y tile : halfs, [96][520] at byte 0   (99840 B)
// A tile : halfs, [512][40] at byte 0   (40960 B, overlaps Y; all x-fragment
//                                        reads complete before Y is written)
// W tile : halfs, [96][32]  at byte 99840 (6144 B)
#define Y_STRIDE 520
#define W_OFF 99840
#define SMEM_SIZE 105984

__device__ __forceinline__ uint32_t smem_to_u32(const void* smem_ptr) {
    uint32_t addr;
    asm("{ .reg .u64 tmp; cvta.to.shared.u64 tmp, %1; cvt.u32.u64 %0, tmp; }"
        : "=r"(addr) : "l"(smem_ptr));
    return addr;
}

__device__ __forceinline__ void ldmatrix_x4(
    uint32_t& r0, uint32_t& r1, uint32_t& r2, uint32_t& r3, uint32_t addr)
{
    asm volatile(
        "ldmatrix.sync.aligned.m8n8.x4.shared.b16 {%0,%1,%2,%3}, [%4];"
        : "=r"(r0), "=r"(r1), "=r"(r2), "=r"(r3) : "r"(addr));
}

__device__ __forceinline__ void mma16816(
    float* d, const uint32_t* a, uint32_t b0, uint32_t b1)
{
    asm volatile(
        "mma.sync.aligned.m16n8k16.row.col.f32.f16.f16.f32 "
        "{%0,%1,%2,%3}, {%4,%5,%6,%7}, {%8,%9}, {%0,%1,%2,%3};"
        : "+f"(d[0]), "+f"(d[1]), "+f"(d[2]), "+f"(d[3])
        : "r"(a[0]), "r"(a[1]), "r"(a[2]), "r"(a[3]), "r"(b0), "r"(b1));
}

// =====================================================================
// Pass 1: one CTA per image row (b, y). 512 threads = 16 warps, occ 2.
//   GEMM (operands swapped): D[n][m] = sum_k W[n][k] * x[m][k]
//     A = W (16n x 16k via ldmatrix), B = x columns (paired LDS.32)
//     => accumulator columns are adjacent pixels -> half2 scatter into Y.
//   Horizontal (kx) fold -> R[(j,ky)] fp16 (vectorized STG.64).
//   Passthrough copy of x (channels 0..31) fused into the A fill.
// =====================================================================
__global__ void __launch_bounds__(512, 2)
msd_pass1(const float* __restrict__ x, const float* __restrict__ W,
          float* __restrict__ out)
{
    extern __shared__ char smem[];
    const uint32_t smem_base = smem_to_u32(smem);
    const int tid = threadIdx.x;
    const int wid = tid >> 5;
    const int lid = tid & 31;
    const int y = blockIdx.x;
    const int b = blockIdx.y;

    __half* ws = reinterpret_cast<__half*>(smem + W_OFF);
    __half* Ys = reinterpret_cast<__half*>(smem);

    // ---- fill W operand: w_s[n][c], n = j*9+ky*3+kx ----
    for (int idx = tid; idx < 96 * 32; idx += 512) {
        int n = idx >> 5, c = idx & 31;
        float w = 0.0f;
        if (n < 90) {
            int j = n / 9, rem = n - j * 9;
            int ky = rem / 3, kx = rem - ky * 3;
            w = W[((j * 32 + c) * 3 + ky) * 3 + kx];
        }
        ws[n * 32 + c] = __float2half(w);
    }

    // ---- fill A operand: thread m owns pixel m (MLP=32, STS.128 x4) ----
    const size_t xbase = (size_t)b * NC * HW * HW + (size_t)y * HW;
    const size_t obase = (size_t)b * 42 * HW * HW + (size_t)y * HW;
    {
        const int m = tid;
        float v[32];
        #pragma unroll
        for (int c = 0; c < 32; c++)
            v[c] = x[xbase + (size_t)c * (HW * HW) + m];
        #pragma unroll
        for (int c = 0; c < 32; c++)
            out[obase + (size_t)c * (HW * HW) + m] = v[c];   // passthrough
        uint32_t h2[16];
        #pragma unroll
        for (int i = 0; i < 16; i++) {
            __half2 p = __floats2half2_rn(v[2 * i], v[2 * i + 1]);
            h2[i] = *reinterpret_cast<uint32_t*>(&p);
        }
        uint4* arow = reinterpret_cast<uint4*>(smem + m * 80);
        #pragma unroll
        for (int k = 0; k < 4; k++)
            arow[k] = make_uint4(h2[4 * k], h2[4 * k + 1],
                                 h2[4 * k + 2], h2[4 * k + 3]);
    }
    __syncthreads();

    // ---- preload x (B operand) fragments: 16 regs, plain LDS.32 pairs ----
    const int mb = wid * 32;
    const int g = lid >> 2, t = lid & 3;
    uint32_t bx[4][2][2];
    #pragma unroll
    for (int m8 = 0; m8 < 4; m8++)
        #pragma unroll
        for (int kh = 0; kh < 2; kh++) {
            const char* bp = smem + (mb + m8 * 8 + g) * 80 + (kh * 16 + 2 * t) * 2;
            bx[m8][kh][0] = *reinterpret_cast<const uint32_t*>(bp);
            bx[m8][kh][1] = *reinterpret_cast<const uint32_t*>(bp + 16);
        }
    __syncthreads();   // all x reads done -> Y may overwrite A region

    // ---- MMA: loop 6 n-tiles of 16; scatter half2 (conflict-free) ----
    const int r8 = lid & 7, t8 = lid >> 3;
    #pragma unroll
    for (int nt = 0; nt < 6; nt++) {
        const int n0 = nt * 16;
        uint32_t aw[2][4];
        #pragma unroll
        for (int kh = 0; kh < 2; kh++) {
            int row = n0 + r8 + (t8 & 1) * 8;
            int col = kh * 16 + (t8 >> 1) * 8;
            ldmatrix_x4(aw[kh][0], aw[kh][1], aw[kh][2], aw[kh][3],
                        smem_base + W_OFF + row * 64 + col * 2);
        }
        float acc[4][4];
        #pragma unroll
        for (int m8 = 0; m8 < 4; m8++) {
            #pragma unroll
            for (int i = 0; i < 4; i++) acc[m8][i] = 0.0f;
            #pragma unroll
            for (int kh = 0; kh < 2; kh++)
                mma16816(acc[m8], aw[kh], bx[m8][kh][0], bx[m8][kh][1]);
        }
        // scatter: rows n0+g / n0+g+8, column pair (2t, 2t+1) of each m8
        #pragma unroll
        for (int m8 = 0; m8 < 4; m8++) {
            int mcol = mb + m8 * 8 + 2 * t;
            __half2 lo = __floats2half2_rn(acc[m8][0], acc[m8][1]);
            __half2 hi = __floats2half2_rn(acc[m8][2], acc[m8][3]);
            *reinterpret_cast<__half2*>(&Ys[(n0 + g) * Y_STRIDE + mcol]) = lo;
            *reinterpret_cast<__half2*>(&Ys[(n0 + g + 8) * Y_STRIDE + mcol]) = hi;
        }
    }
    __syncthreads();

    // ---- horizontal (kx) fold -> R fp16, STG.64 per (plane, quad) ----
    const size_t rowbase = ((size_t)b * HW + y) * HW;
    for (int idx = tid; idx < 30 * 128; idx += 512) {
        int p = idx >> 7;          // plane 0..29  (n = 3p)
        int q = idx & 127;
        int j = p / 3;
        int n = 3 * p;
        int d = j + 1;
        int m0 = q * 4;
        uint2 cc = *reinterpret_cast<const uint2*>(&Ys[(n + 1) * Y_STRIDE + m0]);
        __half2 c01 = *reinterpret_cast<__half2*>(&cc.x);
        __half2 c23 = *reinterpret_cast<__half2*>(&cc.y);
        float a[4];
        a[0] = __low2float(c01);  a[1] = __high2float(c01);
        a[2] = __low2float(c23);  a[3] = __high2float(c23);
        #pragma unroll
        for (int i = 0; i < 4; i++) {
            int ml = m0 + i - d;
            int mr = m0 + i + d;
            if (ml >= 0)  a[i] += __half2float(Ys[n * Y_STRIDE + ml]);
            if (mr < HW)  a[i] += __half2float(Ys[(n + 2) * Y_STRIDE + mr]);
        }
        __half2 o01 = __floats2half2_rn(a[0], a[1]);
        __half2 o23 = __floats2half2_rn(a[2], a[3]);
        uint2 ov = make_uint2(*reinterpret_cast<uint32_t*>(&o01),
                              *reinterpret_cast<uint32_t*>(&o23));
        *reinterpret_cast<uint2*>(
            g_R + (size_t)p * ((size_t)NB * HW * HW) + rowbase + m0) = ov;
    }
}

// =====================================================================
// Pass 2: vertical (ky) fold + bias. 4 pixels per thread, float4 store.
// =====================================================================
__global__ void __launch_bounds__(256)
msd_pass2(const float* __restrict__ bias, float* __restrict__ out)
{
    int idx4 = blockIdx.x * 256 + threadIdx.x;
    int x4 = idx4 & 127;
    int y  = (idx4 >> 7) & 511;
    int t  = idx4 >> 16;
    int j  = t % 10;
    int b  = t / 10;
    int d  = j + 1;
    float bj = __ldg(bias + j);
    float a0 = bj, a1 = bj, a2 = bj, a3 = bj;
    #pragma unroll
    for (int ky = 0; ky < 3; ky++) {
        int y2 = y + (ky - 1) * d;
        if (y2 < 0 || y2 >= HW) continue;
        const __half2* p = reinterpret_cast<const __half2*>(
            g_R + (size_t)(j * 3 + ky) * ((size_t)NB * HW * HW)
                + ((size_t)b * HW + y2) * HW + (size_t)x4 * 4);
        float2 f0 = __half22float2(p[0]);
        float2 f1 = __half22float2(p[1]);
        a0 += f0.x; a1 += f0.y; a2 += f1.x; a3 += f1.y;
    }
    float4 v = make_float4(a0, a1, a2, a3);
    *reinterpret_cast<float4*>(
        out + ((size_t)(b * 42 + 32 + j) * HW + y) * HW + (size_t)x4 * 4) = v;
}

// Tiny no-op: pads launches/call to 5 so ncu (-s 5 -c 1) lands on pass1.
__global__ void msd_noop() {}

// =====================================================================
extern "C" void kernel_launch(void* const* d_in, const int* in_sizes, int n_in,
                              void* d_out, int out_size)
{
    const float* x = nullptr;
    const float* W = nullptr;
    const float* bias = nullptr;
    for (int i = 0; i < n_in; i++) {
        if (in_sizes[i] == 8 * 32 * 512 * 512) x    = (const float*)d_in[i];
        else if (in_sizes[i] == 2880)          W    = (const float*)d_in[i];
        else if (in_sizes[i] == 10)            bias = (const float*)d_in[i];
    }
    float* out = (float*)d_out;

    cudaFuncSetAttribute(msd_pass1,
                         cudaFuncAttributeMaxDynamicSharedMemorySize, SMEM_SIZE);

    dim3 g1(HW, NB);
    msd_pass1<<<g1, 512, SMEM_SIZE>>>(x, W, out);

    int n4 = NB * 10 * HW * HW / 4;          // 5,242,880 quads
    msd_pass2<<<n4 / 256, 256>>>(bias, out);

    msd_noop<<<1, 32>>>();
    msd_noop<<<1, 32>>>();
    msd_noop<<<1, 32>>>();
}

// round 6
// speedup vs baseline: 2.0008x; 1.0645x over previous
#include <cuda_runtime.h>
#include <cuda_bf16.h>
#include <cuda_fp16.h>
#include <cstdint>

#define HW 512
#define NB 8
#define NC 32

// R scratch: 30 planes [j*3+ky][b][y][x] fp16 = 126 MB
__device__ __half g_R[(size_t)30 * NB * HW * HW];

// ---------------- smem layout (pass 1) ----------------
// Tile = 256 output pixels, computed over 288-pixel range (16-px halo).
// Y tile : halfs, [96][296] at byte 0   (56832 B)
// A tile : halfs, [288][40] at byte 0   (23040 B, overlaps Y; all x-fragment
//                                        reads complete before Y is written)
// W tile : halfs, [96][32]  at byte 56832 (6144 B)
#define MTILE 288
#define Y_STRIDE 296
#define W_OFF 56832
#define SMEM_SIZE 62976

__device__ __forceinline__ uint32_t smem_to_u32(const void* smem_ptr) {
    uint32_t addr;
    asm("{ .reg .u64 tmp; cvta.to.shared.u64 tmp, %1; cvt.u32.u64 %0, tmp; }"
        : "=r"(addr) : "l"(smem_ptr));
    return addr;
}

__device__ __forceinline__ void ldmatrix_x4(
    uint32_t& r0, uint32_t& r1, uint32_t& r2, uint32_t& r3, uint32_t addr)
{
    asm volatile(
        "ldmatrix.sync.aligned.m8n8.x4.shared.b16 {%0,%1,%2,%3}, [%4];"
        : "=r"(r0), "=r"(r1), "=r"(r2), "=r"(r3) : "r"(addr));
}

__device__ __forceinline__ void mma16816(
    float* d, const uint32_t* a, uint32_t b0, uint32_t b1)
{
    asm volatile(
        "mma.sync.aligned.m16n8k16.row.col.f32.f16.f16.f32 "
        "{%0,%1,%2,%3}, {%4,%5,%6,%7}, {%8,%9}, {%0,%1,%2,%3};"
        : "+f"(d[0]), "+f"(d[1]), "+f"(d[2]), "+f"(d[3])
        : "r"(a[0]), "r"(a[1]), "r"(a[2]), "r"(a[3]), "r"(b0), "r"(b1));
}

// =====================================================================
// Pass 1: one CTA per 256-pixel half-row. 288 threads = 9 warps, occ 3.
//   GEMM: D[n][m] = sum_k W[n][k] * x[m][k]  over 288-pixel halo range
//   Horizontal (kx) fold -> R[(j,ky)] fp16 for the 256 owned pixels.
//   Passthrough copy of x (channels 0..31) fused into the A fill.
// =====================================================================
__global__ void __launch_bounds__(288, 3)
msd_pass1(const float* __restrict__ x, const float* __restrict__ W,
          float* __restrict__ out)
{
    extern __shared__ char smem[];
    const uint32_t smem_base = smem_to_u32(smem);
    const int tid = threadIdx.x;
    const int wid = tid >> 5;
    const int lid = tid & 31;
    const int P0 = blockIdx.x * 256;      // first owned pixel
    const int y = blockIdx.y;
    const int b = blockIdx.z;

    __half* ws = reinterpret_cast<__half*>(smem + W_OFF);
    __half* Ys = reinterpret_cast<__half*>(smem);

    // ---- fill W operand: w_s[n][c], n = j*9+ky*3+kx ----
    for (int idx = tid; idx < 96 * 32; idx += 288) {
        int n = idx >> 5, c = idx & 31;
        float w = 0.0f;
        if (n < 90) {
            int j = n / 9, rem = n - j * 9;
            int ky = rem / 3, kx = rem - ky * 3;
            w = W[((j * 32 + c) * 3 + ky) * 3 + kx];
        }
        ws[n * 32 + c] = __float2half(w);
    }

    // ---- fill A operand: thread m owns pixel gp = P0-16+m ----
    const size_t xbase = (size_t)b * NC * HW * HW + (size_t)y * HW;
    const size_t obase = (size_t)b * 42 * HW * HW + (size_t)y * HW;
    {
        const int m = tid;
        const int gp = P0 - 16 + m;
        const bool inimg = (gp >= 0) && (gp < HW);
        const bool owned = (m >= 16) && (m < 272);
        #pragma unroll
        for (int ch = 0; ch < 2; ch++) {           // 2 chunks of 16 channels
            float v[16];
            #pragma unroll
            for (int c = 0; c < 16; c++)
                v[c] = inimg
                     ? x[xbase + (size_t)(ch * 16 + c) * (HW * HW) + gp]
                     : 0.0f;
            if (owned) {
                #pragma unroll
                for (int c = 0; c < 16; c++)
                    out[obase + (size_t)(ch * 16 + c) * (HW * HW) + gp] = v[c];
            }
            uint32_t h2[8];
            #pragma unroll
            for (int i = 0; i < 8; i++) {
                __half2 p = __floats2half2_rn(v[2 * i], v[2 * i + 1]);
                h2[i] = *reinterpret_cast<uint32_t*>(&p);
            }
            uint4* arow = reinterpret_cast<uint4*>(smem + m * 80 + ch * 32);
            arow[0] = make_uint4(h2[0], h2[1], h2[2], h2[3]);
            arow[1] = make_uint4(h2[4], h2[5], h2[6], h2[7]);
        }
    }
    __syncthreads();

    // ---- preload x (B operand) fragments: 16 regs, plain LDS.32 pairs ----
    const int mb = wid * 32;
    const int g = lid >> 2, t = lid & 3;
    uint32_t bx[4][2][2];
    #pragma unroll
    for (int m8 = 0; m8 < 4; m8++)
        #pragma unroll
        for (int kh = 0; kh < 2; kh++) {
            const char* bp = smem + (mb + m8 * 8 + g) * 80 + (kh * 16 + 2 * t) * 2;
            bx[m8][kh][0] = *reinterpret_cast<const uint32_t*>(bp);
            bx[m8][kh][1] = *reinterpret_cast<const uint32_t*>(bp + 16);
        }
    __syncthreads();   // all x reads done -> Y may overwrite A region

    // ---- MMA: loop 6 n-tiles of 16; scatter half2 (conflict-free) ----
    const int r8 = lid & 7, t8 = lid >> 3;
    #pragma unroll
    for (int nt = 0; nt < 6; nt++) {
        const int n0 = nt * 16;
        uint32_t aw[2][4];
        #pragma unroll
        for (int kh = 0; kh < 2; kh++) {
            int row = n0 + r8 + (t8 & 1) * 8;
            int col = kh * 16 + (t8 >> 1) * 8;
            ldmatrix_x4(aw[kh][0], aw[kh][1], aw[kh][2], aw[kh][3],
                        smem_base + W_OFF + row * 64 + col * 2);
        }
        float acc[4][4];
        #pragma unroll
        for (int m8 = 0; m8 < 4; m8++) {
            #pragma unroll
            for (int i = 0; i < 4; i++) acc[m8][i] = 0.0f;
            #pragma unroll
            for (int kh = 0; kh < 2; kh++)
                mma16816(acc[m8], aw[kh], bx[m8][kh][0], bx[m8][kh][1]);
        }
        #pragma unroll
        for (int m8 = 0; m8 < 4; m8++) {
            int mcol = mb + m8 * 8 + 2 * t;
            __half2 lo = __floats2half2_rn(acc[m8][0], acc[m8][1]);
            __half2 hi = __floats2half2_rn(acc[m8][2], acc[m8][3]);
            *reinterpret_cast<__half2*>(&Ys[(n0 + g) * Y_STRIDE + mcol]) = lo;
            *reinterpret_cast<__half2*>(&Ys[(n0 + g + 8) * Y_STRIDE + mcol]) = hi;
        }
    }
    __syncthreads();

    // ---- horizontal (kx) fold -> R fp16, STG.64 per (plane, quad) ----
    const size_t rowbase = ((size_t)b * HW + y) * HW;
    for (int idx = tid; idx < 30 * 64; idx += 288) {
        int p = idx >> 6;          // plane 0..29  (n = 3p)
        int q = idx & 63;          // quad within owned 256 pixels
        int j = p / 3;
        int n = 3 * p;
        int d = j + 1;
        int lm = q * 4 + 16;       // local center index of quad start
        uint2 cc = *reinterpret_cast<const uint2*>(&Ys[(n + 1) * Y_STRIDE + lm]);
        __half2 c01 = *reinterpret_cast<__half2*>(&cc.x);
        __half2 c23 = *reinterpret_cast<__half2*>(&cc.y);
        float a[4];
        a[0] = __low2float(c01);  a[1] = __high2float(c01);
        a[2] = __low2float(c23);  a[3] = __high2float(c23);
        #pragma unroll
        for (int i = 0; i < 4; i++) {
            a[i] += __half2float(Ys[n * Y_STRIDE + lm + i - d]);
            a[i] += __half2float(Ys[(n + 2) * Y_STRIDE + lm + i + d]);
        }
        __half2 o01 = __floats2half2_rn(a[0], a[1]);
        __half2 o23 = __floats2half2_rn(a[2], a[3]);
        uint2 ov = make_uint2(*reinterpret_cast<uint32_t*>(&o01),
                              *reinterpret_cast<uint32_t*>(&o23));
        *reinterpret_cast<uint2*>(
            g_R + (size_t)p * ((size_t)NB * HW * HW) + rowbase + P0 + q * 4) = ov;
    }
}

// =====================================================================
// Pass 2: vertical (ky) fold + bias. 4 pixels per thread, float4 store.
// =====================================================================
__global__ void __launch_bounds__(256)
msd_pass2(const float* __restrict__ bias, float* __restrict__ out)
{
    int idx4 = blockIdx.x * 256 + threadIdx.x;
    int x4 = idx4 & 127;
    int y  = (idx4 >> 7) & 511;
    int t  = idx4 >> 16;
    int j  = t % 10;
    int b  = t / 10;
    int d  = j + 1;
    float bj = __ldg(bias + j);
    float a0 = bj, a1 = bj, a2 = bj, a3 = bj;
    #pragma unroll
    for (int ky = 0; ky < 3; ky++) {
        int y2 = y + (ky - 1) * d;
        if (y2 < 0 || y2 >= HW) continue;
        const __half2* p = reinterpret_cast<const __half2*>(
            g_R + (size_t)(j * 3 + ky) * ((size_t)NB * HW * HW)
                + ((size_t)b * HW + y2) * HW + (size_t)x4 * 4);
        float2 f0 = __half22float2(p[0]);
        float2 f1 = __half22float2(p[1]);
        a0 += f0.x; a1 += f0.y; a2 += f1.x; a3 += f1.y;
    }
    float4 v = make_float4(a0, a1, a2, a3);
    *reinterpret_cast<float4*>(
        out + ((size_t)(b * 42 + 32 + j) * HW + y) * HW + (size_t)x4 * 4) = v;
}

// Tiny no-op: pads launches so ncu (-s 5 -c 1) lands on pass1 next replay.
__global__ void msd_noop() {}

// =====================================================================
extern "C" void kernel_launch(void* const* d_in, const int* in_sizes, int n_in,
                              void* d_out, int out_size)
{
    const float* x = nullptr;
    const float* W = nullptr;
    const float* bias = nullptr;
    for (int i = 0; i < n_in; i++) {
        if (in_sizes[i] == 8 * 32 * 512 * 512) x    = (const float*)d_in[i];
        else if (in_sizes[i] == 2880)          W    = (const float*)d_in[i];
        else if (in_sizes[i] == 10)            bias = (const float*)d_in[i];
    }
    float* out = (float*)d_out;

    cudaFuncSetAttribute(msd_pass1,
                         cudaFuncAttributeMaxDynamicSharedMemorySize, SMEM_SIZE);

    dim3 g1(2, HW, NB);
    msd_pass1<<<g1, MTILE, SMEM_SIZE>>>(x, W, out);

    int n4 = NB * 10 * HW * HW / 4;          // 5,242,880 quads
    msd_pass2<<<n4 / 256, 256>>>(bias, out);

    msd_noop<<<1, 32>>>();
    msd_noop<<<1, 32>>>();
}